// round 11
// baseline (speedup 1.0000x reference)
#include <cuda_runtime.h>
#include <limits.h>

#define BB 8
#define NN 8192
#define MM 2048
#define CC 64
#define KK 64
#define R2 0.01f
#define ROWF 68            // floats per row: [f0..f63, x, y, z, pad] (272B)
#define NCELL 1000         // 10x10x10 grid, cell size 0.1
#define RREACH 0.1002f     // conservative cell reach (covers d2 rounding slack)
#define HCAP 128           // per-query candidate-hit cap (max expected ~75)
#define MAXCOL 16          // max (cx,cy) columns per query (4x4)

// Scratch (no cudaMalloc allowed)
__device__ float  g_ptsT[BB * NN * ROWF];        // transposed point rows
__device__ int    g_cellcnt[BB * NCELL];         // zero-init; re-zeroed by scan
__device__ int    g_cellstart[BB * (NCELL + 1)];
__device__ int    g_cellofs[BB * NCELL];
__device__ float4 g_cellpts[BB * NN];            // (x,y,z, idx-bits) cell-sorted

__device__ __forceinline__ int cell_of(float x, float y, float z)
{
    int cx = (int)(x * 10.0f); cx = min(max(cx, 0), 9);
    int cy = (int)(y * 10.0f); cy = min(max(cy, 0), 9);
    int cz = (int)(z * 10.0f); cz = min(max(cz, 0), 9);
    return (cx * 10 + cy) * 10 + cz;
}

// ---------------------------------------------------------------------------
// K1: transpose (rows [f0..f63, x, y, z, pad]) + cell histogram (R8 passing).
// ---------------------------------------------------------------------------
__global__ void __launch_bounds__(256) transpose_hist_kernel(
    const float* __restrict__ xyz, const float* __restrict__ feat)
{
    __shared__ float s[64][65];
    __shared__ float sxyz[3][64];
    const int b   = blockIdx.y;
    const int n0  = blockIdx.x * 64;
    const int tid = threadIdx.x;
    const int p   = tid & 63;
    const int c0  = tid >> 6;

    #pragma unroll
    for (int cc = 0; cc < 64; cc += 4) {
        const int c = cc + c0;
        s[c][p] = feat[((size_t)(b * 64 + c)) * NN + n0 + p];
    }
    if (tid < 192) {
        const int c  = tid >> 6;
        const int pp = tid & 63;
        sxyz[c][pp] = xyz[((size_t)(b * 3 + c)) * NN + n0 + pp];
    }
    __syncthreads();

    if (tid < 64) {
        const int cell = cell_of(sxyz[0][tid], sxyz[1][tid], sxyz[2][tid]);
        atomicAdd(&g_cellcnt[b * NCELL + cell], 1);
    }

    for (int f = tid; f < 64 * 17; f += 256) {
        const int pp = f / 17;
        const int j  = f - pp * 17;
        float4 v;
        if (j < 16) {
            const int c = 4 * j;
            v.x = s[c][pp]; v.y = s[c + 1][pp]; v.z = s[c + 2][pp]; v.w = s[c + 3][pp];
        } else {
            v.x = sxyz[0][pp]; v.y = sxyz[1][pp]; v.z = sxyz[2][pp]; v.w = 0.0f;
        }
        ((float4*)(g_ptsT + ((size_t)(b * NN + n0 + pp)) * ROWF))[j] = v;
    }
}

// ---------------------------------------------------------------------------
// K2: scan per batch (re-zeros g_cellcnt for replay invariance).
// ---------------------------------------------------------------------------
__global__ void __launch_bounds__(1024) scan_kernel()
{
    __shared__ int s[1024];
    const int b   = blockIdx.x;
    const int tid = threadIdx.x;
    const int v = (tid < NCELL) ? g_cellcnt[b * NCELL + tid] : 0;
    if (tid < NCELL) g_cellcnt[b * NCELL + tid] = 0;
    s[tid] = v;
    __syncthreads();
    #pragma unroll
    for (int d = 1; d < 1024; d <<= 1) {
        const int t = (tid >= d) ? s[tid - d] : 0;
        __syncthreads();
        s[tid] += t;
        __syncthreads();
    }
    if (tid < NCELL) {
        const int excl = s[tid] - v;
        g_cellstart[b * (NCELL + 1) + tid] = excl;
        g_cellofs[b * NCELL + tid] = excl;
    }
    if (tid == NCELL - 1)
        g_cellstart[b * (NCELL + 1) + NCELL] = s[tid];
}

// ---------------------------------------------------------------------------
// K3: scatter points into cell-sorted array.
// ---------------------------------------------------------------------------
__global__ void __launch_bounds__(1024) scatter_kernel(const float* __restrict__ xyz)
{
    const int b = blockIdx.y;
    const int n = blockIdx.x * 1024 + threadIdx.x;
    const float x = xyz[(b * 3 + 0) * NN + n];
    const float y = xyz[(b * 3 + 1) * NN + n];
    const float z = xyz[(b * 3 + 2) * NN + n];
    const int pos = atomicAdd(&g_cellofs[b * NCELL + cell_of(x, y, z)], 1);
    g_cellpts[b * NN + pos] = make_float4(x, y, z, __int_as_float(n));
}

// ---------------------------------------------------------------------------
// Bitonic sorts (unchanged)
// ---------------------------------------------------------------------------
__device__ __forceinline__ void cmpex(int& v, int e_lane_bits, int j, int k, int lane)
{
    const int pv = __shfl_xor_sync(0xffffffffu, v, j);
    const bool up = ((e_lane_bits & k) == 0);
    const bool lo = ((lane & j) == 0);
    v = ((lo == up) ? min(v, pv) : max(v, pv));
}

__device__ __forceinline__ void bitonic64(int& v0, int& v1, int lane)
{
    #pragma unroll
    for (int k = 2; k <= 64; k <<= 1) {
        #pragma unroll
        for (int j = k >> 1; j > 0; j >>= 1) {
            if (j >= 32) {
                const int a = min(v0, v1), b2 = max(v0, v1);
                v0 = a; v1 = b2;
            } else {
                cmpex(v0, lane,      j, k, lane);
                cmpex(v1, 32 + lane, j, k, lane);
            }
        }
    }
}

__device__ __forceinline__ void bitonic128(int& v0, int& v1, int& v2, int& v3, int lane)
{
    #pragma unroll
    for (int k = 2; k <= 128; k <<= 1) {
        #pragma unroll
        for (int j = k >> 1; j > 0; j >>= 1) {
            if (j == 64) {
                int a, b2;
                a = min(v0, v2); b2 = max(v0, v2); v0 = a; v2 = b2;
                a = min(v1, v3); b2 = max(v1, v3); v1 = a; v3 = b2;
            } else if (j == 32) {
                const bool upA = (((lane)      & k) == 0);
                const bool upB = (((64 + lane) & k) == 0);
                int a, b2;
                a = min(v0, v1); b2 = max(v0, v1);
                v0 = upA ? a : b2;  v1 = upA ? b2 : a;
                a = min(v2, v3); b2 = max(v2, v3);
                v2 = upB ? a : b2;  v3 = upB ? b2 : a;
            } else {
                cmpex(v0, lane,      j, k, lane);
                cmpex(v1, 32 + lane, j, k, lane);
                cmpex(v2, 64 + lane, j, k, lane);
                cmpex(v3, 96 + lane, j, k, lane);
            }
        }
    }
}

// ---------------------------------------------------------------------------
// K4: FUSED ball query + gather. One block per (b, m).
// Block-wide candidate scan (same candidate SET as before; order made
// deterministic by the ascending bitonic sort). d2 predicate byte-identical
// (bit-exact vs reference). Then gather via the proven swizzled-smem path.
// ---------------------------------------------------------------------------
__global__ void __launch_bounds__(256) bq_gather_kernel(
    const float* __restrict__ new_xyz, float* __restrict__ out)
{
    __shared__ int   sidx[64];
    __shared__ float srow[64][ROWF];
    __shared__ int   hlist[HCAP];
    __shared__ int   sstart[MAXCOL];
    __shared__ int   soff[MAXCOL + 1];
    __shared__ int   s_total;
    __shared__ int   s_cnt;

    const int b    = blockIdx.y;
    const int m    = blockIdx.x;
    const int tid  = threadIdx.x;
    const int lane = tid & 31;

    const float qx = new_xyz[(b * 3 + 0) * MM + m];
    const float qy = new_xyz[(b * 3 + 1) * MM + m];
    const float qz = new_xyz[(b * 3 + 2) * MM + m];
    const float sq = __fadd_rn(__fadd_rn(__fmul_rn(qx, qx), __fmul_rn(qy, qy)),
                               __fmul_rn(qz, qz));

    // ---- span setup (warp 0) ----
    if (tid < 32) {
        if (tid == 0) s_cnt = 0;
        const int xlo = max(0, (int)floorf((qx - RREACH) * 10.0f));
        const int xhi = min(9, (int)floorf((qx + RREACH) * 10.0f));
        const int ylo = max(0, (int)floorf((qy - RREACH) * 10.0f));
        const int yhi = min(9, (int)floorf((qy + RREACH) * 10.0f));
        const int zlo = max(0, (int)floorf((qz - RREACH) * 10.0f));
        const int zhi = min(9, (int)floorf((qz + RREACH) * 10.0f));
        const int ynum = yhi - ylo + 1;
        const int ncol = (xhi - xlo + 1) * ynum;

        int sc = 0, len = 0;
        if (lane < ncol) {
            const int cx = xlo + lane / ynum;
            const int cy = ylo + (lane - (lane / ynum) * ynum);
            const int base = b * (NCELL + 1) + (cx * 10 + cy) * 10;
            sc  = g_cellstart[base + zlo];
            len = g_cellstart[base + zhi + 1] - sc;
        }
        int inc = len;
        #pragma unroll
        for (int d = 1; d < 32; d <<= 1) {
            const int t = __shfl_up_sync(0xffffffffu, inc, d);
            if (lane >= d) inc += t;
        }
        const int total = __shfl_sync(0xffffffffu, inc, 31);
        if (lane < ncol) {
            sstart[lane] = sc;
            soff[lane]   = inc - len;
        }
        if (lane == 0) { soff[ncol] = total; s_total = total; }
    }
    __syncthreads();

    // ---- block-wide candidate scan ----
    const int total = s_total;
    const unsigned lt_mask = (lane == 0) ? 0u : (0xffffffffu >> (32 - lane));

    for (int p0 = 0; p0 < total; p0 += 256) {
        const int pos = p0 + tid;
        bool in = false;
        int  pidx = 0;
        if (pos < total) {
            int cur = 0;
            while (pos >= soff[cur + 1]) ++cur;
            const int src = sstart[cur] + (pos - soff[cur]);
            const float4 p = g_cellpts[b * NN + src];
            const float sp = __fadd_rn(
                __fadd_rn(__fmul_rn(p.x, p.x), __fmul_rn(p.y, p.y)),
                __fmul_rn(p.z, p.z));
            float dt = __fmul_rn(qx, p.x);
            dt = __fmaf_rn(qy, p.y, dt);
            dt = __fmaf_rn(qz, p.z, dt);
            const float d2 = __fsub_rn(__fadd_rn(sq, sp), __fmul_rn(2.0f, dt));
            in = d2 < R2;
            pidx = __float_as_int(p.w);
        }
        const unsigned mask = __ballot_sync(0xffffffffu, in);
        int base = 0;
        if (lane == 0 && mask) base = atomicAdd(&s_cnt, __popc(mask));
        base = __shfl_sync(0xffffffffu, base, 0);
        if (in) {
            const int posw = base + __popc(mask & lt_mask);
            if (posw < HCAP) hlist[posw] = pidx;
        }
    }
    __syncthreads();

    // ---- warp 0 sorts hits ascending, writes sidx (padded with first) ----
    if (tid < 32) {
        int cnt = s_cnt;
        if (cnt > HCAP) cnt = HCAP;
        int v0 = (lane < cnt)      ? hlist[lane]      : INT_MAX;
        int v1 = (32 + lane < cnt) ? hlist[32 + lane] : INT_MAX;
        if (cnt <= 64) {
            bitonic64(v0, v1, lane);
        } else {
            int v2 = (64 + lane < cnt) ? hlist[64 + lane] : INT_MAX;
            int v3 = (96 + lane < cnt) ? hlist[96 + lane] : INT_MAX;
            bitonic128(v0, v1, v2, v3, lane);
        }
        const int f0 = __shfl_sync(0xffffffffu, v0, 0);
        const int first = (cnt == 0) ? 0 : f0;
        sidx[lane]      = (lane < cnt)      ? v0 : first;
        sidx[32 + lane] = (32 + lane < cnt) ? v1 : first;
    }
    __syncthreads();

    // ---- gather: stage 64 rows (swizzled, conflict-free; proven R6-R10) ----
    for (int f = tid; f < 64 * 17; f += 256) {
        const int r = f / 17;
        const int j = f - r * 17;
        float4 v = ((const float4*)(g_ptsT +
                    (size_t)(b * NN + sidx[r]) * ROWF))[j];
        if (j < 16) {
            if (r & 1) { float t = v.x; v.x = v.y; v.y = t;
                         t = v.z; v.z = v.w; v.w = t; }
            if (r & 2) { float t = v.x; v.x = v.z; v.z = t;
                         t = v.y; v.y = v.w; v.w = t; }
            const int jq = j ^ ((r >> 2) & 7);
            *((float4*)&srow[r][4 * jq]) = v;
        } else {
            srow[r][64] = v.x;
            srow[r][65] = v.y;
            srow[r][66] = v.z;
        }
    }
    __syncthreads();

    // ---- output: conflict-free column reads + streaming STG.128 ----
    for (int t = tid; t < 67 * 8; t += 256) {
        const int c   = t >> 3;
        const int k4h = t & 7;
        float sub = 0.0f;
        if (c < 3) sub = new_xyz[(b * 3 + c) * MM + m];
        #pragma unroll
        for (int h = 0; h < 2; ++h) {
            const int k4 = k4h + 8 * h;
            const int k  = 4 * k4;
            float4 v;
            if (c < 3) {
                v.x = srow[k + 0][64 + c] - sub;
                v.y = srow[k + 1][64 + c] - sub;
                v.z = srow[k + 2][64 + c] - sub;
                v.w = srow[k + 3][64 + c] - sub;
            } else {
                const int cf = c - 3;
                v.x = srow[k + 0][cf ^ ((k + 0) & 31)];
                v.y = srow[k + 1][cf ^ ((k + 1) & 31)];
                v.z = srow[k + 2][cf ^ ((k + 2) & 31)];
                v.w = srow[k + 3][cf ^ ((k + 3) & 31)];
            }
            __stcs(((float4*)(out + (((size_t)b * 67 + c) * MM + m) * 64)) + k4, v);
        }
    }
}

// ---------------------------------------------------------------------------
extern "C" void kernel_launch(void* const* d_in, const int* in_sizes, int n_in,
                              void* d_out, int out_size)
{
    const float* new_xyz = (const float*)d_in[0];  // (8, 3, 2048)
    const float* xyz     = (const float*)d_in[1];  // (8, 3, 8192)
    const float* feature = (const float*)d_in[2];  // (8, 64, 8192)
    float* out = (float*)d_out;                    // (8, 67, 2048, 64)

    transpose_hist_kernel<<<dim3(NN / 64, BB), 256>>>(xyz, feature);
    scan_kernel<<<BB, 1024>>>();
    scatter_kernel<<<dim3(NN / 1024, BB), 1024>>>(xyz);
    bq_gather_kernel<<<dim3(MM, BB), 256>>>(new_xyz, out);
}

// round 12
// speedup vs baseline: 1.1128x; 1.1128x over previous
#include <cuda_runtime.h>
#include <limits.h>

#define BB 8
#define NN 8192
#define MM 2048
#define CC 64
#define KK 64
#define R2 0.01f
#define ROWF 68            // floats per row: [f0..f63, x, y, z, pad] (272B)
#define NCELL 1000         // 10x10x10 grid, cell size 0.1
#define RREACH 0.1002f     // conservative cell reach (covers d2 rounding slack)
#define HCAP 128           // per-query candidate-hit cap (max expected ~75)
#define MAXCOL 16          // max (cx,cy) columns per query (4x4)
#define NBQBLK ((MM / 8) * BB)     // 2048 ballquery blocks
#define NTRBLK ((NN / 64) * BB)    // 1024 transpose blocks

// Scratch (no cudaMalloc allowed)
__device__ float  g_ptsT[BB * NN * ROWF];        // transposed point rows
__device__ int    g_idx[BB * MM * KK];           // neighbor indices
__device__ int    g_cellcnt[BB * NCELL];         // zero-init; re-zeroed by scan
__device__ int    g_cellstart[BB * (NCELL + 1)];
__device__ int    g_cellofs[BB * NCELL];
__device__ float4 g_cellpts[BB * NN];            // (x,y,z, idx-bits) cell-sorted

__device__ __forceinline__ int cell_of(float x, float y, float z)
{
    int cx = (int)(x * 10.0f); cx = min(max(cx, 0), 9);
    int cy = (int)(y * 10.0f); cy = min(max(cy, 0), 9);
    int cz = (int)(z * 10.0f); cz = min(max(cz, 0), 9);
    return (cx * 10 + cy) * 10 + cz;
}

// ---------------------------------------------------------------------------
// K1: standalone cell histogram (coalesced loads + cheap REDG atomics).
// ---------------------------------------------------------------------------
__global__ void __launch_bounds__(256) hist_kernel(const float* __restrict__ xyz)
{
    const int b = blockIdx.y;
    const int n = blockIdx.x * 256 + threadIdx.x;
    const float x = xyz[(b * 3 + 0) * NN + n];
    const float y = xyz[(b * 3 + 1) * NN + n];
    const float z = xyz[(b * 3 + 2) * NN + n];
    atomicAdd(&g_cellcnt[b * NCELL + cell_of(x, y, z)], 1);
}

// ---------------------------------------------------------------------------
// K2: scan per batch (re-zeros g_cellcnt for replay invariance).
// ---------------------------------------------------------------------------
__global__ void __launch_bounds__(1024) scan_kernel()
{
    __shared__ int s[1024];
    const int b   = blockIdx.x;
    const int tid = threadIdx.x;
    const int v = (tid < NCELL) ? g_cellcnt[b * NCELL + tid] : 0;
    if (tid < NCELL) g_cellcnt[b * NCELL + tid] = 0;
    s[tid] = v;
    __syncthreads();
    #pragma unroll
    for (int d = 1; d < 1024; d <<= 1) {
        const int t = (tid >= d) ? s[tid - d] : 0;
        __syncthreads();
        s[tid] += t;
        __syncthreads();
    }
    if (tid < NCELL) {
        const int excl = s[tid] - v;
        g_cellstart[b * (NCELL + 1) + tid] = excl;
        g_cellofs[b * NCELL + tid] = excl;
    }
    if (tid == NCELL - 1)
        g_cellstart[b * (NCELL + 1) + NCELL] = s[tid];
}

// ---------------------------------------------------------------------------
// K3: scatter points into cell-sorted array.
// ---------------------------------------------------------------------------
__global__ void __launch_bounds__(1024) scatter_kernel(const float* __restrict__ xyz)
{
    const int b = blockIdx.y;
    const int n = blockIdx.x * 1024 + threadIdx.x;
    const float x = xyz[(b * 3 + 0) * NN + n];
    const float y = xyz[(b * 3 + 1) * NN + n];
    const float z = xyz[(b * 3 + 2) * NN + n];
    const int pos = atomicAdd(&g_cellofs[b * NCELL + cell_of(x, y, z)], 1);
    g_cellpts[b * NN + pos] = make_float4(x, y, z, __int_as_float(n));
}

// ---------------------------------------------------------------------------
// Bitonic sorts (unchanged)
// ---------------------------------------------------------------------------
__device__ __forceinline__ void cmpex(int& v, int e_lane_bits, int j, int k, int lane)
{
    const int pv = __shfl_xor_sync(0xffffffffu, v, j);
    const bool up = ((e_lane_bits & k) == 0);
    const bool lo = ((lane & j) == 0);
    v = ((lo == up) ? min(v, pv) : max(v, pv));
}

__device__ __forceinline__ void bitonic64(int& v0, int& v1, int lane)
{
    #pragma unroll
    for (int k = 2; k <= 64; k <<= 1) {
        #pragma unroll
        for (int j = k >> 1; j > 0; j >>= 1) {
            if (j >= 32) {
                const int a = min(v0, v1), b2 = max(v0, v1);
                v0 = a; v1 = b2;
            } else {
                cmpex(v0, lane,      j, k, lane);
                cmpex(v1, 32 + lane, j, k, lane);
            }
        }
    }
}

__device__ __forceinline__ void bitonic128(int& v0, int& v1, int& v2, int& v3, int lane)
{
    #pragma unroll
    for (int k = 2; k <= 128; k <<= 1) {
        #pragma unroll
        for (int j = k >> 1; j > 0; j >>= 1) {
            if (j == 64) {
                int a, b2;
                a = min(v0, v2); b2 = max(v0, v2); v0 = a; v2 = b2;
                a = min(v1, v3); b2 = max(v1, v3); v1 = a; v3 = b2;
            } else if (j == 32) {
                const bool upA = (((lane)      & k) == 0);
                const bool upB = (((64 + lane) & k) == 0);
                int a, b2;
                a = min(v0, v1); b2 = max(v0, v1);
                v0 = upA ? a : b2;  v1 = upA ? b2 : a;
                a = min(v2, v3); b2 = max(v2, v3);
                v2 = upB ? a : b2;  v3 = upB ? b2 : a;
            } else {
                cmpex(v0, lane,      j, k, lane);
                cmpex(v1, 32 + lane, j, k, lane);
                cmpex(v2, 64 + lane, j, k, lane);
                cmpex(v3, 96 + lane, j, k, lane);
            }
        }
    }
}

// ---------------------------------------------------------------------------
// K4: FUSED ballquery + transpose, 2:1 INTERLEAVED block families so every
// wave mixes issue-bound (bq) and DRAM-bound (transpose) blocks.
// Both branches byte-identical to passing R10 (d2 bit-exact vs reference).
// ---------------------------------------------------------------------------
union SmemK4 {
    struct { float s[64][65]; float sxyz[3][64]; } t;
    struct { int hlist[8][HCAP]; int sstart[8][MAXCOL]; int soff[8][MAXCOL + 1]; } q;
};

__global__ void __launch_bounds__(256) fused_bq_transpose_kernel(
    const float* __restrict__ xyz, const float* __restrict__ feat,
    const float* __restrict__ new_xyz)
{
    __shared__ SmemK4 sm;
    const int tid = threadIdx.x;

    // 2:1 interleave: group g supplies bq blocks (2g, 2g+1) and transpose g.
    const int g = blockIdx.x / 3;
    const int r = blockIdx.x - g * 3;

    if (r < 2) {
        // ================= ball query =================
        const int bqid = 2 * g + r;             // 0..NBQBLK-1
        const int b    = bqid >> 8;             // 256 blocks per batch
        const int warp = tid >> 5;
        const int lane = tid & 31;
        const int m    = (bqid & 255) * 8 + warp;
        const int q    = b * MM + m;

        const float qx = new_xyz[(b * 3 + 0) * MM + m];
        const float qy = new_xyz[(b * 3 + 1) * MM + m];
        const float qz = new_xyz[(b * 3 + 2) * MM + m];
        const float sq = __fadd_rn(__fadd_rn(__fmul_rn(qx, qx), __fmul_rn(qy, qy)),
                                   __fmul_rn(qz, qz));

        const int xlo = max(0, (int)floorf((qx - RREACH) * 10.0f));
        const int xhi = min(9, (int)floorf((qx + RREACH) * 10.0f));
        const int ylo = max(0, (int)floorf((qy - RREACH) * 10.0f));
        const int yhi = min(9, (int)floorf((qy + RREACH) * 10.0f));
        const int zlo = max(0, (int)floorf((qz - RREACH) * 10.0f));
        const int zhi = min(9, (int)floorf((qz + RREACH) * 10.0f));

        const int ynum = yhi - ylo + 1;
        const int ncol = (xhi - xlo + 1) * ynum;

        int sc = 0, len = 0;
        if (lane < ncol) {
            const int cx = xlo + lane / ynum;
            const int cy = ylo + (lane - (lane / ynum) * ynum);
            const int base = b * (NCELL + 1) + (cx * 10 + cy) * 10;
            sc  = g_cellstart[base + zlo];
            len = g_cellstart[base + zhi + 1] - sc;
        }
        int inc = len;
        #pragma unroll
        for (int d = 1; d < 32; d <<= 1) {
            const int t = __shfl_up_sync(0xffffffffu, inc, d);
            if (lane >= d) inc += t;
        }
        const int total = __shfl_sync(0xffffffffu, inc, 31);
        if (lane < ncol) {
            sm.q.sstart[warp][lane] = sc;
            sm.q.soff[warp][lane]   = inc - len;
        }
        if (lane == 0) sm.q.soff[warp][ncol] = total;
        __syncwarp();

        const unsigned lt_mask = (lane == 0) ? 0u : (0xffffffffu >> (32 - lane));
        int cnt = 0;
        int cur = 0;

        for (int p0 = 0; p0 < total; p0 += 32) {
            const int pos = p0 + lane;
            const bool valid = pos < total;
            bool in = false;
            int  pidx = 0;
            if (valid) {
                while (pos >= sm.q.soff[warp][cur + 1]) ++cur;
                const int src = sm.q.sstart[warp][cur] + (pos - sm.q.soff[warp][cur]);
                const float4 p = g_cellpts[b * NN + src];
                const float sp = __fadd_rn(
                    __fadd_rn(__fmul_rn(p.x, p.x), __fmul_rn(p.y, p.y)),
                    __fmul_rn(p.z, p.z));
                float dt = __fmul_rn(qx, p.x);
                dt = __fmaf_rn(qy, p.y, dt);
                dt = __fmaf_rn(qz, p.z, dt);
                const float d2 = __fsub_rn(__fadd_rn(sq, sp), __fmul_rn(2.0f, dt));
                in = d2 < R2;
                pidx = __float_as_int(p.w);
            }
            const unsigned mask = __ballot_sync(0xffffffffu, in);
            if (in) {
                const int posw = cnt + __popc(mask & lt_mask);
                if (posw < HCAP) sm.q.hlist[warp][posw] = pidx;
            }
            cnt += __popc(mask);
        }
        if (cnt > HCAP) cnt = HCAP;

        int v0 = (lane < cnt)      ? sm.q.hlist[warp][lane]      : INT_MAX;
        int v1 = (32 + lane < cnt) ? sm.q.hlist[warp][32 + lane] : INT_MAX;
        if (cnt <= 64) {
            bitonic64(v0, v1, lane);
        } else {
            int v2 = (64 + lane < cnt) ? sm.q.hlist[warp][64 + lane] : INT_MAX;
            int v3 = (96 + lane < cnt) ? sm.q.hlist[warp][96 + lane] : INT_MAX;
            bitonic128(v0, v1, v2, v3, lane);
        }

        const int f0 = __shfl_sync(0xffffffffu, v0, 0);
        const int first = (cnt == 0) ? 0 : f0;
        g_idx[q * 64 + lane]      = (lane < cnt)      ? v0 : first;
        g_idx[q * 64 + 32 + lane] = (32 + lane < cnt) ? v1 : first;
    } else {
        // ================= transpose =================
        const int t_id = g;                     // 0..NTRBLK-1
        const int b    = t_id >> 7;             // 128 blocks per batch
        const int n0   = (t_id & 127) * 64;
        const int p    = tid & 63;
        const int c0   = tid >> 6;

        #pragma unroll
        for (int cc = 0; cc < 64; cc += 4) {
            const int c = cc + c0;
            sm.t.s[c][p] = feat[((size_t)(b * 64 + c)) * NN + n0 + p];
        }
        if (tid < 192) {
            const int c  = tid >> 6;
            const int pp = tid & 63;
            sm.t.sxyz[c][pp] = xyz[((size_t)(b * 3 + c)) * NN + n0 + pp];
        }
        __syncthreads();

        for (int f = tid; f < 64 * 17; f += 256) {
            const int pp = f / 17;
            const int j  = f - pp * 17;
            float4 v;
            if (j < 16) {
                const int c = 4 * j;
                v.x = sm.t.s[c][pp];     v.y = sm.t.s[c + 1][pp];
                v.z = sm.t.s[c + 2][pp]; v.w = sm.t.s[c + 3][pp];
            } else {
                v.x = sm.t.sxyz[0][pp]; v.y = sm.t.sxyz[1][pp];
                v.z = sm.t.sxyz[2][pp]; v.w = 0.0f;
            }
            ((float4*)(g_ptsT + ((size_t)(b * NN + n0 + pp)) * ROWF))[j] = v;
        }
    }
}

// ---------------------------------------------------------------------------
// Gather + concat (unchanged from passing R10).
// ---------------------------------------------------------------------------
__global__ void __launch_bounds__(256) gather_kernel(
    const float* __restrict__ new_xyz, float* __restrict__ out)
{
    __shared__ int   sidx[64];
    __shared__ float srow[64][ROWF];
    const int b   = blockIdx.y;
    const int m   = blockIdx.x;
    const int tid = threadIdx.x;
    const int q   = b * MM + m;

    if (tid < 64) sidx[tid] = g_idx[q * 64 + tid];
    __syncthreads();

    for (int f = tid; f < 64 * 17; f += 256) {
        const int r = f / 17;
        const int j = f - r * 17;
        float4 v = ((const float4*)(g_ptsT +
                    (size_t)(b * NN + sidx[r]) * ROWF))[j];
        if (j < 16) {
            if (r & 1) { float t = v.x; v.x = v.y; v.y = t;
                         t = v.z; v.z = v.w; v.w = t; }
            if (r & 2) { float t = v.x; v.x = v.z; v.z = t;
                         t = v.y; v.y = v.w; v.w = t; }
            const int jq = j ^ ((r >> 2) & 7);
            *((float4*)&srow[r][4 * jq]) = v;
        } else {
            srow[r][64] = v.x;
            srow[r][65] = v.y;
            srow[r][66] = v.z;
        }
    }
    __syncthreads();

    for (int t = tid; t < 67 * 8; t += 256) {
        const int c   = t >> 3;
        const int k4h = t & 7;
        float sub = 0.0f;
        if (c < 3) sub = new_xyz[(b * 3 + c) * MM + m];
        #pragma unroll
        for (int h = 0; h < 2; ++h) {
            const int k4 = k4h + 8 * h;
            const int k  = 4 * k4;
            float4 v;
            if (c < 3) {
                v.x = srow[k + 0][64 + c] - sub;
                v.y = srow[k + 1][64 + c] - sub;
                v.z = srow[k + 2][64 + c] - sub;
                v.w = srow[k + 3][64 + c] - sub;
            } else {
                const int cf = c - 3;
                v.x = srow[k + 0][cf ^ ((k + 0) & 31)];
                v.y = srow[k + 1][cf ^ ((k + 1) & 31)];
                v.z = srow[k + 2][cf ^ ((k + 2) & 31)];
                v.w = srow[k + 3][cf ^ ((k + 3) & 31)];
            }
            __stcs(((float4*)(out + (((size_t)b * 67 + c) * MM + m) * 64)) + k4, v);
        }
    }
}

// ---------------------------------------------------------------------------
extern "C" void kernel_launch(void* const* d_in, const int* in_sizes, int n_in,
                              void* d_out, int out_size)
{
    const float* new_xyz = (const float*)d_in[0];  // (8, 3, 2048)
    const float* xyz     = (const float*)d_in[1];  // (8, 3, 8192)
    const float* feature = (const float*)d_in[2];  // (8, 64, 8192)
    float* out = (float*)d_out;                    // (8, 67, 2048, 64)

    hist_kernel<<<dim3(NN / 256, BB), 256>>>(xyz);
    scan_kernel<<<BB, 1024>>>();
    scatter_kernel<<<dim3(NN / 1024, BB), 1024>>>(xyz);
    fused_bq_transpose_kernel<<<NBQBLK + NTRBLK, 256>>>(xyz, feature, new_xyz);
    gather_kernel<<<dim3(MM, BB), 256>>>(new_xyz, out);
}

// round 13
// speedup vs baseline: 1.1360x; 1.0208x over previous
#include <cuda_runtime.h>
#include <limits.h>

#define BB 8
#define NN 8192
#define MM 2048
#define CC 64
#define KK 64
#define R2 0.01f
#define ROWF 68            // floats per row: [f0..f63, x, y, z, pad] (272B)
#define NZC 40             // z cells (cell_z = 0.025); xy stays 10x10 (0.1)
#define NCELL (100 * NZC)  // 4000 cells per batch
#define RREACH 0.1002f     // conservative cell reach (covers d2 rounding slack)
#define HCAP 128           // per-query candidate-hit cap (max expected ~75)
#define MAXCOL 16          // max (cx,cy) columns per query (4x4)
#define NBQBLK ((MM / 8) * BB)     // 2048 ballquery blocks
#define NTRBLK ((NN / 64) * BB)    // 1024 transpose blocks

// Scratch (no cudaMalloc allowed)
__device__ float  g_ptsT[BB * NN * ROWF];        // transposed point rows
__device__ int    g_idx[BB * MM * KK];           // neighbor indices
__device__ int    g_cellcnt[BB * NCELL];         // zero-init; re-zeroed by scan
__device__ int    g_cellstart[BB * (NCELL + 1)];
__device__ int    g_cellofs[BB * NCELL];
__device__ float4 g_cellpts[BB * NN];            // (x,y,z, idx-bits) cell-sorted

__device__ __forceinline__ int cell_of(float x, float y, float z)
{
    int cx = (int)(x * 10.0f);         cx = min(max(cx, 0), 9);
    int cy = (int)(y * 10.0f);         cy = min(max(cy, 0), 9);
    int cz = (int)(z * (float)NZC);    cz = min(max(cz, 0), NZC - 1);
    return (cx * 10 + cy) * NZC + cz;
}

// ---------------------------------------------------------------------------
// K1: standalone cell histogram (coalesced loads + cheap REDG atomics).
// ---------------------------------------------------------------------------
__global__ void __launch_bounds__(256) hist_kernel(const float* __restrict__ xyz)
{
    const int b = blockIdx.y;
    const int n = blockIdx.x * 256 + threadIdx.x;
    const float x = xyz[(b * 3 + 0) * NN + n];
    const float y = xyz[(b * 3 + 1) * NN + n];
    const float z = xyz[(b * 3 + 2) * NN + n];
    atomicAdd(&g_cellcnt[b * NCELL + cell_of(x, y, z)], 1);
}

// ---------------------------------------------------------------------------
// K2: scan per batch over 4000 cells. Thread t owns int4 of cells 4t..4t+3:
// local prefix + block Hillis-Steele over thread sums. Re-zeros g_cellcnt.
// ---------------------------------------------------------------------------
__global__ void __launch_bounds__(1024) scan_kernel()
{
    __shared__ int s[1024];
    const int b   = blockIdx.x;
    const int tid = threadIdx.x;

    int4 v = make_int4(0, 0, 0, 0);
    if (tid < NCELL / 4) {
        v = ((int4*)(g_cellcnt + b * NCELL))[tid];
        ((int4*)(g_cellcnt + b * NCELL))[tid] = make_int4(0, 0, 0, 0);
    }
    const int tsum = v.x + v.y + v.z + v.w;
    s[tid] = tsum;
    __syncthreads();
    #pragma unroll
    for (int d = 1; d < 1024; d <<= 1) {
        const int t = (tid >= d) ? s[tid - d] : 0;
        __syncthreads();
        s[tid] += t;
        __syncthreads();
    }
    if (tid < NCELL / 4) {
        const int excl = s[tid] - tsum;
        const int cbase = 4 * tid;
        int e0 = excl;
        int e1 = excl + v.x;
        int e2 = e1 + v.y;
        int e3 = e2 + v.z;
        g_cellstart[b * (NCELL + 1) + cbase + 0] = e0;
        g_cellstart[b * (NCELL + 1) + cbase + 1] = e1;
        g_cellstart[b * (NCELL + 1) + cbase + 2] = e2;
        g_cellstart[b * (NCELL + 1) + cbase + 3] = e3;
        g_cellofs[b * NCELL + cbase + 0] = e0;
        g_cellofs[b * NCELL + cbase + 1] = e1;
        g_cellofs[b * NCELL + cbase + 2] = e2;
        g_cellofs[b * NCELL + cbase + 3] = e3;
    }
    if (tid == NCELL / 4 - 1)
        g_cellstart[b * (NCELL + 1) + NCELL] = s[tid];
}

// ---------------------------------------------------------------------------
// K3: scatter points into cell-sorted array.
// ---------------------------------------------------------------------------
__global__ void __launch_bounds__(1024) scatter_kernel(const float* __restrict__ xyz)
{
    const int b = blockIdx.y;
    const int n = blockIdx.x * 1024 + threadIdx.x;
    const float x = xyz[(b * 3 + 0) * NN + n];
    const float y = xyz[(b * 3 + 1) * NN + n];
    const float z = xyz[(b * 3 + 2) * NN + n];
    const int pos = atomicAdd(&g_cellofs[b * NCELL + cell_of(x, y, z)], 1);
    g_cellpts[b * NN + pos] = make_float4(x, y, z, __int_as_float(n));
}

// ---------------------------------------------------------------------------
// Bitonic sorts (unchanged)
// ---------------------------------------------------------------------------
__device__ __forceinline__ void cmpex(int& v, int e_lane_bits, int j, int k, int lane)
{
    const int pv = __shfl_xor_sync(0xffffffffu, v, j);
    const bool up = ((e_lane_bits & k) == 0);
    const bool lo = ((lane & j) == 0);
    v = ((lo == up) ? min(v, pv) : max(v, pv));
}

__device__ __forceinline__ void bitonic64(int& v0, int& v1, int lane)
{
    #pragma unroll
    for (int k = 2; k <= 64; k <<= 1) {
        #pragma unroll
        for (int j = k >> 1; j > 0; j >>= 1) {
            if (j >= 32) {
                const int a = min(v0, v1), b2 = max(v0, v1);
                v0 = a; v1 = b2;
            } else {
                cmpex(v0, lane,      j, k, lane);
                cmpex(v1, 32 + lane, j, k, lane);
            }
        }
    }
}

__device__ __forceinline__ void bitonic128(int& v0, int& v1, int& v2, int& v3, int lane)
{
    #pragma unroll
    for (int k = 2; k <= 128; k <<= 1) {
        #pragma unroll
        for (int j = k >> 1; j > 0; j >>= 1) {
            if (j == 64) {
                int a, b2;
                a = min(v0, v2); b2 = max(v0, v2); v0 = a; v2 = b2;
                a = min(v1, v3); b2 = max(v1, v3); v1 = a; v3 = b2;
            } else if (j == 32) {
                const bool upA = (((lane)      & k) == 0);
                const bool upB = (((64 + lane) & k) == 0);
                int a, b2;
                a = min(v0, v1); b2 = max(v0, v1);
                v0 = upA ? a : b2;  v1 = upA ? b2 : a;
                a = min(v2, v3); b2 = max(v2, v3);
                v2 = upB ? a : b2;  v3 = upB ? b2 : a;
            } else {
                cmpex(v0, lane,      j, k, lane);
                cmpex(v1, 32 + lane, j, k, lane);
                cmpex(v2, 64 + lane, j, k, lane);
                cmpex(v3, 96 + lane, j, k, lane);
            }
        }
    }
}

// ---------------------------------------------------------------------------
// K4: FUSED ballquery (blocks 0..NBQBLK-1) + transpose (rest) — R10 layout.
// d2 predicate byte-identical (bit-exact vs reference).
// ---------------------------------------------------------------------------
union SmemK4 {
    struct { float s[64][65]; float sxyz[3][64]; } t;
    struct { int hlist[8][HCAP]; int sstart[8][MAXCOL]; int soff[8][MAXCOL + 1]; } q;
};

__global__ void __launch_bounds__(256) fused_bq_transpose_kernel(
    const float* __restrict__ xyz, const float* __restrict__ feat,
    const float* __restrict__ new_xyz)
{
    __shared__ SmemK4 sm;
    const int tid = threadIdx.x;

    if (blockIdx.x < NBQBLK) {
        // ================= ball query =================
        const int bqid = blockIdx.x;
        const int b    = bqid >> 8;             // 256 blocks per batch
        const int warp = tid >> 5;
        const int lane = tid & 31;
        const int m    = (bqid & 255) * 8 + warp;
        const int q    = b * MM + m;

        const float qx = new_xyz[(b * 3 + 0) * MM + m];
        const float qy = new_xyz[(b * 3 + 1) * MM + m];
        const float qz = new_xyz[(b * 3 + 2) * MM + m];
        const float sq = __fadd_rn(__fadd_rn(__fmul_rn(qx, qx), __fmul_rn(qy, qy)),
                                   __fmul_rn(qz, qz));

        const int xlo = max(0, (int)floorf((qx - RREACH) * 10.0f));
        const int xhi = min(9, (int)floorf((qx + RREACH) * 10.0f));
        const int ylo = max(0, (int)floorf((qy - RREACH) * 10.0f));
        const int yhi = min(9, (int)floorf((qy + RREACH) * 10.0f));
        const int zlo = max(0, (int)floorf((qz - RREACH) * (float)NZC));
        const int zhi = min(NZC - 1, (int)floorf((qz + RREACH) * (float)NZC));

        const int ynum = yhi - ylo + 1;
        const int ncol = (xhi - xlo + 1) * ynum;

        int sc = 0, len = 0;
        if (lane < ncol) {
            const int cx = xlo + lane / ynum;
            const int cy = ylo + (lane - (lane / ynum) * ynum);
            const int base = b * (NCELL + 1) + (cx * 10 + cy) * NZC;
            sc  = g_cellstart[base + zlo];
            len = g_cellstart[base + zhi + 1] - sc;
        }
        int inc = len;
        #pragma unroll
        for (int d = 1; d < 32; d <<= 1) {
            const int t = __shfl_up_sync(0xffffffffu, inc, d);
            if (lane >= d) inc += t;
        }
        const int total = __shfl_sync(0xffffffffu, inc, 31);
        if (lane < ncol) {
            sm.q.sstart[warp][lane] = sc;
            sm.q.soff[warp][lane]   = inc - len;
        }
        if (lane == 0) sm.q.soff[warp][ncol] = total;
        __syncwarp();

        const unsigned lt_mask = (lane == 0) ? 0u : (0xffffffffu >> (32 - lane));
        int cnt = 0;
        int cur = 0;

        for (int p0 = 0; p0 < total; p0 += 32) {
            const int pos = p0 + lane;
            const bool valid = pos < total;
            bool in = false;
            int  pidx = 0;
            if (valid) {
                while (pos >= sm.q.soff[warp][cur + 1]) ++cur;
                const int src = sm.q.sstart[warp][cur] + (pos - sm.q.soff[warp][cur]);
                const float4 p = g_cellpts[b * NN + src];
                const float sp = __fadd_rn(
                    __fadd_rn(__fmul_rn(p.x, p.x), __fmul_rn(p.y, p.y)),
                    __fmul_rn(p.z, p.z));
                float dt = __fmul_rn(qx, p.x);
                dt = __fmaf_rn(qy, p.y, dt);
                dt = __fmaf_rn(qz, p.z, dt);
                const float d2 = __fsub_rn(__fadd_rn(sq, sp), __fmul_rn(2.0f, dt));
                in = d2 < R2;
                pidx = __float_as_int(p.w);
            }
            const unsigned mask = __ballot_sync(0xffffffffu, in);
            if (in) {
                const int posw = cnt + __popc(mask & lt_mask);
                if (posw < HCAP) sm.q.hlist[warp][posw] = pidx;
            }
            cnt += __popc(mask);
        }
        if (cnt > HCAP) cnt = HCAP;

        int v0 = (lane < cnt)      ? sm.q.hlist[warp][lane]      : INT_MAX;
        int v1 = (32 + lane < cnt) ? sm.q.hlist[warp][32 + lane] : INT_MAX;
        if (cnt <= 64) {
            bitonic64(v0, v1, lane);
        } else {
            int v2 = (64 + lane < cnt) ? sm.q.hlist[warp][64 + lane] : INT_MAX;
            int v3 = (96 + lane < cnt) ? sm.q.hlist[warp][96 + lane] : INT_MAX;
            bitonic128(v0, v1, v2, v3, lane);
        }

        const int f0 = __shfl_sync(0xffffffffu, v0, 0);
        const int first = (cnt == 0) ? 0 : f0;
        g_idx[q * 64 + lane]      = (lane < cnt)      ? v0 : first;
        g_idx[q * 64 + 32 + lane] = (32 + lane < cnt) ? v1 : first;
    } else {
        // ================= transpose =================
        const int t_id = blockIdx.x - NBQBLK;
        const int b    = t_id >> 7;             // 128 blocks per batch
        const int n0   = (t_id & 127) * 64;
        const int p    = tid & 63;
        const int c0   = tid >> 6;

        #pragma unroll
        for (int cc = 0; cc < 64; cc += 4) {
            const int c = cc + c0;
            sm.t.s[c][p] = feat[((size_t)(b * 64 + c)) * NN + n0 + p];
        }
        if (tid < 192) {
            const int c  = tid >> 6;
            const int pp = tid & 63;
            sm.t.sxyz[c][pp] = xyz[((size_t)(b * 3 + c)) * NN + n0 + pp];
        }
        __syncthreads();

        for (int f = tid; f < 64 * 17; f += 256) {
            const int pp = f / 17;
            const int j  = f - pp * 17;
            float4 v;
            if (j < 16) {
                const int c = 4 * j;
                v.x = sm.t.s[c][pp];     v.y = sm.t.s[c + 1][pp];
                v.z = sm.t.s[c + 2][pp]; v.w = sm.t.s[c + 3][pp];
            } else {
                v.x = sm.t.sxyz[0][pp]; v.y = sm.t.sxyz[1][pp];
                v.z = sm.t.sxyz[2][pp]; v.w = 0.0f;
            }
            ((float4*)(g_ptsT + ((size_t)(b * NN + n0 + pp)) * ROWF))[j] = v;
        }
    }
}

// ---------------------------------------------------------------------------
// Gather + concat (unchanged from passing R10).
// ---------------------------------------------------------------------------
__global__ void __launch_bounds__(256) gather_kernel(
    const float* __restrict__ new_xyz, float* __restrict__ out)
{
    __shared__ int   sidx[64];
    __shared__ float srow[64][ROWF];
    const int b   = blockIdx.y;
    const int m   = blockIdx.x;
    const int tid = threadIdx.x;
    const int q   = b * MM + m;

    if (tid < 64) sidx[tid] = g_idx[q * 64 + tid];
    __syncthreads();

    for (int f = tid; f < 64 * 17; f += 256) {
        const int r = f / 17;
        const int j = f - r * 17;
        float4 v = ((const float4*)(g_ptsT +
                    (size_t)(b * NN + sidx[r]) * ROWF))[j];
        if (j < 16) {
            if (r & 1) { float t = v.x; v.x = v.y; v.y = t;
                         t = v.z; v.z = v.w; v.w = t; }
            if (r & 2) { float t = v.x; v.x = v.z; v.z = t;
                         t = v.y; v.y = v.w; v.w = t; }
            const int jq = j ^ ((r >> 2) & 7);
            *((float4*)&srow[r][4 * jq]) = v;
        } else {
            srow[r][64] = v.x;
            srow[r][65] = v.y;
            srow[r][66] = v.z;
        }
    }
    __syncthreads();

    for (int t = tid; t < 67 * 8; t += 256) {
        const int c   = t >> 3;
        const int k4h = t & 7;
        float sub = 0.0f;
        if (c < 3) sub = new_xyz[(b * 3 + c) * MM + m];
        #pragma unroll
        for (int h = 0; h < 2; ++h) {
            const int k4 = k4h + 8 * h;
            const int k  = 4 * k4;
            float4 v;
            if (c < 3) {
                v.x = srow[k + 0][64 + c] - sub;
                v.y = srow[k + 1][64 + c] - sub;
                v.z = srow[k + 2][64 + c] - sub;
                v.w = srow[k + 3][64 + c] - sub;
            } else {
                const int cf = c - 3;
                v.x = srow[k + 0][cf ^ ((k + 0) & 31)];
                v.y = srow[k + 1][cf ^ ((k + 1) & 31)];
                v.z = srow[k + 2][cf ^ ((k + 2) & 31)];
                v.w = srow[k + 3][cf ^ ((k + 3) & 31)];
            }
            __stcs(((float4*)(out + (((size_t)b * 67 + c) * MM + m) * 64)) + k4, v);
        }
    }
}

// ---------------------------------------------------------------------------
extern "C" void kernel_launch(void* const* d_in, const int* in_sizes, int n_in,
                              void* d_out, int out_size)
{
    const float* new_xyz = (const float*)d_in[0];  // (8, 3, 2048)
    const float* xyz     = (const float*)d_in[1];  // (8, 3, 8192)
    const float* feature = (const float*)d_in[2];  // (8, 64, 8192)
    float* out = (float*)d_out;                    // (8, 67, 2048, 64)

    hist_kernel<<<dim3(NN / 256, BB), 256>>>(xyz);
    scan_kernel<<<BB, 1024>>>();
    scatter_kernel<<<dim3(NN / 1024, BB), 1024>>>(xyz);
    fused_bq_transpose_kernel<<<NBQBLK + NTRBLK, 256>>>(xyz, feature, new_xyz);
    gather_kernel<<<dim3(MM, BB), 256>>>(new_xyz, out);
}

// round 14
// speedup vs baseline: 1.2549x; 1.1046x over previous
#include <cuda_runtime.h>
#include <limits.h>

#define BB 8
#define NN 8192
#define MM 2048
#define CC 64
#define KK 64
#define R2 0.01f
#define NZC 40             // z cells (cell_z = 0.025); xy stays 10x10 (0.1)
#define NCELL (100 * NZC)  // 4000 cells per batch
#define RREACH 0.1002f     // conservative cell reach (covers d2 rounding slack)
#define HCAP 128           // per-query candidate-hit cap (max expected ~75)
#define MAXCOL 16          // max (cx,cy) columns per query (4x4)
#define NBQBLK ((MM / 8) * BB)     // 2048 ballquery blocks
#define NTRBLK ((NN / 64) * BB)    // 1024 transpose blocks

// Scratch (no cudaMalloc allowed)
__device__ float  g_feat[BB * NN * 64];          // feature rows, 256B each
__device__ float4 g_xyzw[BB * NN];               // xyz per point (16B)
__device__ int    g_idx[BB * MM * KK];           // neighbor indices
__device__ int    g_cellcnt[BB * NCELL];         // zero-init; re-zeroed by scan
__device__ int    g_cellstart[BB * (NCELL + 1)];
__device__ int    g_cellofs[BB * NCELL];
__device__ float4 g_cellpts[BB * NN];            // (x,y,z, idx-bits) cell-sorted

__device__ __forceinline__ int cell_of(float x, float y, float z)
{
    int cx = (int)(x * 10.0f);         cx = min(max(cx, 0), 9);
    int cy = (int)(y * 10.0f);         cy = min(max(cy, 0), 9);
    int cz = (int)(z * (float)NZC);    cz = min(max(cz, 0), NZC - 1);
    return (cx * 10 + cy) * NZC + cz;
}

// ---------------------------------------------------------------------------
// K1: standalone cell histogram.
// ---------------------------------------------------------------------------
__global__ void __launch_bounds__(256) hist_kernel(const float* __restrict__ xyz)
{
    const int b = blockIdx.y;
    const int n = blockIdx.x * 256 + threadIdx.x;
    const float x = xyz[(b * 3 + 0) * NN + n];
    const float y = xyz[(b * 3 + 1) * NN + n];
    const float z = xyz[(b * 3 + 2) * NN + n];
    atomicAdd(&g_cellcnt[b * NCELL + cell_of(x, y, z)], 1);
}

// ---------------------------------------------------------------------------
// K2: scan per batch over 4000 cells (int4 per thread). Re-zeros g_cellcnt.
// ---------------------------------------------------------------------------
__global__ void __launch_bounds__(1024) scan_kernel()
{
    __shared__ int s[1024];
    const int b   = blockIdx.x;
    const int tid = threadIdx.x;

    int4 v = make_int4(0, 0, 0, 0);
    if (tid < NCELL / 4) {
        v = ((int4*)(g_cellcnt + b * NCELL))[tid];
        ((int4*)(g_cellcnt + b * NCELL))[tid] = make_int4(0, 0, 0, 0);
    }
    const int tsum = v.x + v.y + v.z + v.w;
    s[tid] = tsum;
    __syncthreads();
    #pragma unroll
    for (int d = 1; d < 1024; d <<= 1) {
        const int t = (tid >= d) ? s[tid - d] : 0;
        __syncthreads();
        s[tid] += t;
        __syncthreads();
    }
    if (tid < NCELL / 4) {
        const int excl = s[tid] - tsum;
        const int cbase = 4 * tid;
        int e0 = excl;
        int e1 = excl + v.x;
        int e2 = e1 + v.y;
        int e3 = e2 + v.z;
        g_cellstart[b * (NCELL + 1) + cbase + 0] = e0;
        g_cellstart[b * (NCELL + 1) + cbase + 1] = e1;
        g_cellstart[b * (NCELL + 1) + cbase + 2] = e2;
        g_cellstart[b * (NCELL + 1) + cbase + 3] = e3;
        g_cellofs[b * NCELL + cbase + 0] = e0;
        g_cellofs[b * NCELL + cbase + 1] = e1;
        g_cellofs[b * NCELL + cbase + 2] = e2;
        g_cellofs[b * NCELL + cbase + 3] = e3;
    }
    if (tid == NCELL / 4 - 1)
        g_cellstart[b * (NCELL + 1) + NCELL] = s[tid];
}

// ---------------------------------------------------------------------------
// K3: scatter points into cell-sorted array.
// ---------------------------------------------------------------------------
__global__ void __launch_bounds__(1024) scatter_kernel(const float* __restrict__ xyz)
{
    const int b = blockIdx.y;
    const int n = blockIdx.x * 1024 + threadIdx.x;
    const float x = xyz[(b * 3 + 0) * NN + n];
    const float y = xyz[(b * 3 + 1) * NN + n];
    const float z = xyz[(b * 3 + 2) * NN + n];
    const int pos = atomicAdd(&g_cellofs[b * NCELL + cell_of(x, y, z)], 1);
    g_cellpts[b * NN + pos] = make_float4(x, y, z, __int_as_float(n));
}

// ---------------------------------------------------------------------------
// Bitonic sorts (unchanged)
// ---------------------------------------------------------------------------
__device__ __forceinline__ void cmpex(int& v, int e_lane_bits, int j, int k, int lane)
{
    const int pv = __shfl_xor_sync(0xffffffffu, v, j);
    const bool up = ((e_lane_bits & k) == 0);
    const bool lo = ((lane & j) == 0);
    v = ((lo == up) ? min(v, pv) : max(v, pv));
}

__device__ __forceinline__ void bitonic64(int& v0, int& v1, int lane)
{
    #pragma unroll
    for (int k = 2; k <= 64; k <<= 1) {
        #pragma unroll
        for (int j = k >> 1; j > 0; j >>= 1) {
            if (j >= 32) {
                const int a = min(v0, v1), b2 = max(v0, v1);
                v0 = a; v1 = b2;
            } else {
                cmpex(v0, lane,      j, k, lane);
                cmpex(v1, 32 + lane, j, k, lane);
            }
        }
    }
}

__device__ __forceinline__ void bitonic128(int& v0, int& v1, int& v2, int& v3, int lane)
{
    #pragma unroll
    for (int k = 2; k <= 128; k <<= 1) {
        #pragma unroll
        for (int j = k >> 1; j > 0; j >>= 1) {
            if (j == 64) {
                int a, b2;
                a = min(v0, v2); b2 = max(v0, v2); v0 = a; v2 = b2;
                a = min(v1, v3); b2 = max(v1, v3); v1 = a; v3 = b2;
            } else if (j == 32) {
                const bool upA = (((lane)      & k) == 0);
                const bool upB = (((64 + lane) & k) == 0);
                int a, b2;
                a = min(v0, v1); b2 = max(v0, v1);
                v0 = upA ? a : b2;  v1 = upA ? b2 : a;
                a = min(v2, v3); b2 = max(v2, v3);
                v2 = upB ? a : b2;  v3 = upB ? b2 : a;
            } else {
                cmpex(v0, lane,      j, k, lane);
                cmpex(v1, 32 + lane, j, k, lane);
                cmpex(v2, 64 + lane, j, k, lane);
                cmpex(v3, 96 + lane, j, k, lane);
            }
        }
    }
}

// ---------------------------------------------------------------------------
// K4: FUSED ballquery (blocks 0..NBQBLK-1) + transpose (rest).
// bq byte-identical to passing R13 (d2 bit-exact). Transpose targets
// g_feat (256B rows) + g_xyzw.
// ---------------------------------------------------------------------------
union SmemK4 {
    struct { float s[64][65]; float sxyz[3][64]; } t;
    struct { int hlist[8][HCAP]; int sstart[8][MAXCOL]; int soff[8][MAXCOL + 1]; } q;
};

__global__ void __launch_bounds__(256) fused_bq_transpose_kernel(
    const float* __restrict__ xyz, const float* __restrict__ feat,
    const float* __restrict__ new_xyz)
{
    __shared__ SmemK4 sm;
    const int tid = threadIdx.x;

    if (blockIdx.x < NBQBLK) {
        // ================= ball query =================
        const int bqid = blockIdx.x;
        const int b    = bqid >> 8;
        const int warp = tid >> 5;
        const int lane = tid & 31;
        const int m    = (bqid & 255) * 8 + warp;
        const int q    = b * MM + m;

        const float qx = new_xyz[(b * 3 + 0) * MM + m];
        const float qy = new_xyz[(b * 3 + 1) * MM + m];
        const float qz = new_xyz[(b * 3 + 2) * MM + m];
        const float sq = __fadd_rn(__fadd_rn(__fmul_rn(qx, qx), __fmul_rn(qy, qy)),
                                   __fmul_rn(qz, qz));

        const int xlo = max(0, (int)floorf((qx - RREACH) * 10.0f));
        const int xhi = min(9, (int)floorf((qx + RREACH) * 10.0f));
        const int ylo = max(0, (int)floorf((qy - RREACH) * 10.0f));
        const int yhi = min(9, (int)floorf((qy + RREACH) * 10.0f));
        const int zlo = max(0, (int)floorf((qz - RREACH) * (float)NZC));
        const int zhi = min(NZC - 1, (int)floorf((qz + RREACH) * (float)NZC));

        const int ynum = yhi - ylo + 1;
        const int ncol = (xhi - xlo + 1) * ynum;

        int sc = 0, len = 0;
        if (lane < ncol) {
            const int cx = xlo + lane / ynum;
            const int cy = ylo + (lane - (lane / ynum) * ynum);
            const int base = b * (NCELL + 1) + (cx * 10 + cy) * NZC;
            sc  = g_cellstart[base + zlo];
            len = g_cellstart[base + zhi + 1] - sc;
        }
        int inc = len;
        #pragma unroll
        for (int d = 1; d < 32; d <<= 1) {
            const int t = __shfl_up_sync(0xffffffffu, inc, d);
            if (lane >= d) inc += t;
        }
        const int total = __shfl_sync(0xffffffffu, inc, 31);
        if (lane < ncol) {
            sm.q.sstart[warp][lane] = sc;
            sm.q.soff[warp][lane]   = inc - len;
        }
        if (lane == 0) sm.q.soff[warp][ncol] = total;
        __syncwarp();

        const unsigned lt_mask = (lane == 0) ? 0u : (0xffffffffu >> (32 - lane));
        int cnt = 0;
        int cur = 0;

        for (int p0 = 0; p0 < total; p0 += 32) {
            const int pos = p0 + lane;
            const bool valid = pos < total;
            bool in = false;
            int  pidx = 0;
            if (valid) {
                while (pos >= sm.q.soff[warp][cur + 1]) ++cur;
                const int src = sm.q.sstart[warp][cur] + (pos - sm.q.soff[warp][cur]);
                const float4 p = g_cellpts[b * NN + src];
                const float sp = __fadd_rn(
                    __fadd_rn(__fmul_rn(p.x, p.x), __fmul_rn(p.y, p.y)),
                    __fmul_rn(p.z, p.z));
                float dt = __fmul_rn(qx, p.x);
                dt = __fmaf_rn(qy, p.y, dt);
                dt = __fmaf_rn(qz, p.z, dt);
                const float d2 = __fsub_rn(__fadd_rn(sq, sp), __fmul_rn(2.0f, dt));
                in = d2 < R2;
                pidx = __float_as_int(p.w);
            }
            const unsigned mask = __ballot_sync(0xffffffffu, in);
            if (in) {
                const int posw = cnt + __popc(mask & lt_mask);
                if (posw < HCAP) sm.q.hlist[warp][posw] = pidx;
            }
            cnt += __popc(mask);
        }
        if (cnt > HCAP) cnt = HCAP;

        int v0 = (lane < cnt)      ? sm.q.hlist[warp][lane]      : INT_MAX;
        int v1 = (32 + lane < cnt) ? sm.q.hlist[warp][32 + lane] : INT_MAX;
        if (cnt <= 64) {
            bitonic64(v0, v1, lane);
        } else {
            int v2 = (64 + lane < cnt) ? sm.q.hlist[warp][64 + lane] : INT_MAX;
            int v3 = (96 + lane < cnt) ? sm.q.hlist[warp][96 + lane] : INT_MAX;
            bitonic128(v0, v1, v2, v3, lane);
        }

        const int f0 = __shfl_sync(0xffffffffu, v0, 0);
        const int first = (cnt == 0) ? 0 : f0;
        g_idx[q * 64 + lane]      = (lane < cnt)      ? v0 : first;
        g_idx[q * 64 + 32 + lane] = (32 + lane < cnt) ? v1 : first;
    } else {
        // ================= transpose =================
        const int t_id = blockIdx.x - NBQBLK;
        const int b    = t_id >> 7;
        const int n0   = (t_id & 127) * 64;
        const int p    = tid & 63;
        const int c0   = tid >> 6;

        #pragma unroll
        for (int cc = 0; cc < 64; cc += 4) {
            const int c = cc + c0;
            sm.t.s[c][p] = feat[((size_t)(b * 64 + c)) * NN + n0 + p];
        }
        if (tid < 192) {
            const int c  = tid >> 6;
            const int pp = tid & 63;
            sm.t.sxyz[c][pp] = xyz[((size_t)(b * 3 + c)) * NN + n0 + pp];
        }
        __syncthreads();

        // features: 64 rows x 16 quads (256B rows)
        for (int f = tid; f < 64 * 16; f += 256) {
            const int pp = f >> 4;
            const int j  = f & 15;
            const int c  = 4 * j;
            float4 v;
            v.x = sm.t.s[c][pp];     v.y = sm.t.s[c + 1][pp];
            v.z = sm.t.s[c + 2][pp]; v.w = sm.t.s[c + 3][pp];
            ((float4*)(g_feat + (((size_t)(b * NN + n0 + pp)) << 6)))[j] = v;
        }
        // xyz
        if (tid < 64)
            g_xyzw[b * NN + n0 + tid] =
                make_float4(sm.t.sxyz[0][tid], sm.t.sxyz[1][tid],
                            sm.t.sxyz[2][tid], 0.0f);
    }
}

// ---------------------------------------------------------------------------
// Gather + concat: 256B feature rows + separate xyz float4. Swizzled smem
// (64x64, conflict-free column reads, verified permutation).
// ---------------------------------------------------------------------------
__global__ void __launch_bounds__(256) gather_kernel(
    const float* __restrict__ new_xyz, float* __restrict__ out)
{
    __shared__ int   sidx[64];
    __shared__ float srow[64][64];
    __shared__ float4 sxyz4[64];
    const int b   = blockIdx.y;
    const int m   = blockIdx.x;
    const int tid = threadIdx.x;
    const int q   = b * MM + m;

    if (tid < 64) sidx[tid] = g_idx[q * 64 + tid];
    __syncthreads();

    if (tid < 64) sxyz4[tid] = g_xyzw[b * NN + sidx[tid]];

    // stage features: 64 rows x 16 quads; each warp-instr covers 2 whole rows
    for (int f = tid; f < 64 * 16; f += 256) {
        const int r = f >> 4;
        const int j = f & 15;
        float4 v = ((const float4*)(g_feat +
                    (((size_t)(b * NN + sidx[r])) << 6)))[j];
        // component XOR-permute by r&3: w[t] = v[t ^ (r&3)]
        if (r & 1) { float t = v.x; v.x = v.y; v.y = t;
                     t = v.z; v.z = v.w; v.w = t; }
        if (r & 2) { float t = v.x; v.x = v.z; v.z = t;
                     t = v.y; v.y = v.w; v.w = t; }
        const int jq = j ^ ((r >> 2) & 7);
        *((float4*)&srow[r][4 * jq]) = v;
    }
    __syncthreads();

    const float* sxyzf = (const float*)sxyz4;

    // output: tasks (c, k4h 0..7); conflict-free column LDS + streaming STG.128
    for (int t = tid; t < 67 * 8; t += 256) {
        const int c   = t >> 3;
        const int k4h = t & 7;
        float sub = 0.0f;
        if (c < 3) sub = new_xyz[(b * 3 + c) * MM + m];
        #pragma unroll
        for (int h = 0; h < 2; ++h) {
            const int k4 = k4h + 8 * h;
            const int k  = 4 * k4;
            float4 v;
            if (c < 3) {
                v.x = sxyzf[4 * (k + 0) + c] - sub;
                v.y = sxyzf[4 * (k + 1) + c] - sub;
                v.z = sxyzf[4 * (k + 2) + c] - sub;
                v.w = sxyzf[4 * (k + 3) + c] - sub;
            } else {
                const int cf = c - 3;
                v.x = srow[k + 0][cf ^ ((k + 0) & 31)];
                v.y = srow[k + 1][cf ^ ((k + 1) & 31)];
                v.z = srow[k + 2][cf ^ ((k + 2) & 31)];
                v.w = srow[k + 3][cf ^ ((k + 3) & 31)];
            }
            __stcs(((float4*)(out + (((size_t)b * 67 + c) * MM + m) * 64)) + k4, v);
        }
    }
}

// ---------------------------------------------------------------------------
extern "C" void kernel_launch(void* const* d_in, const int* in_sizes, int n_in,
                              void* d_out, int out_size)
{
    const float* new_xyz = (const float*)d_in[0];  // (8, 3, 2048)
    const float* xyz     = (const float*)d_in[1];  // (8, 3, 8192)
    const float* feature = (const float*)d_in[2];  // (8, 64, 8192)
    float* out = (float*)d_out;                    // (8, 67, 2048, 64)

    hist_kernel<<<dim3(NN / 256, BB), 256>>>(xyz);
    scan_kernel<<<BB, 1024>>>();
    scatter_kernel<<<dim3(NN / 1024, BB), 1024>>>(xyz);
    fused_bq_transpose_kernel<<<NBQBLK + NTRBLK, 256>>>(xyz, feature, new_xyz);
    gather_kernel<<<dim3(MM, BB), 256>>>(new_xyz, out);
}